// round 12
// baseline (speedup 1.0000x reference)
#include <cuda_runtime.h>
#include <cuda_fp16.h>
#include <math.h>
#include <float.h>
#include <stdint.h>

#define N_NODES 100000
#define IN_DIM  256
#define HID     128
#define OUT_DIM 40
#define E_MAX   3200000
#define NB_SCAN ((N_NODES + 1023) / 1024)   // 98

typedef unsigned long long u64;

// ---------------- scratch (device globals, allocation-free) ----------------
__device__ int   g_cnt_in[N_NODES];
__device__ int   g_cnt_out[N_NODES];
__device__ int   g_incl[N_NODES];
__device__ int   g_bsum[NB_SCAN];
__device__ int   g_boff[NB_SCAN];
__device__ int   g_row_off[N_NODES + 1];
__device__ int   g_cursor[N_NODES];
__device__ int   g_csr_src[E_MAX];
__device__ __half g_w1h[(size_t)IN_DIM * HID];     // W1 fp16 [k][n]
__device__ __half g_w2h[(size_t)HID * OUT_DIM];    // W2 fp16 [k][n]
__device__ __half g_h1[(size_t)N_NODES * HID];     // h1 fp16 (layer-1 pre-agg)
__device__ __half g_x1h[(size_t)N_NODES * HID];    // x1 fp16 (gemm2 input)
__device__ __half g_x2[(size_t)N_NODES * OUT_DIM]; // x2 fp16 (layer-2 pre-agg)

// ---------------- helpers ----------------
__device__ __forceinline__ uint32_t h2u(__half2 h) {
    uint32_t u;
    memcpy(&u, &h, 4);
    return u;
}
__device__ __forceinline__ uint32_t smem_u32(const void* p) {
    uint32_t a;
    asm("{ .reg .u64 t; cvta.to.shared.u64 t, %1; cvt.u32.u64 %0, t; }" : "=r"(a) : "l"(p));
    return a;
}
// mma.sync m16n8k16 f16 x f16 -> f32
__device__ __forceinline__ void mma16816(float* c, uint32_t a0, uint32_t a1, uint32_t a2,
                                         uint32_t a3, uint32_t b0, uint32_t b1) {
    asm volatile("mma.sync.aligned.m16n8k16.row.col.f32.f16.f16.f32 "
                 "{%0,%1,%2,%3}, {%4,%5,%6,%7}, {%8,%9}, {%0,%1,%2,%3};"
                 : "+f"(c[0]), "+f"(c[1]), "+f"(c[2]), "+f"(c[3])
                 : "r"(a0), "r"(a1), "r"(a2), "r"(a3), "r"(b0), "r"(b1));
}

// ---------------------------------------------------------------------------
__global__ void zero_counts_kernel() {
    int i = blockIdx.x * blockDim.x + threadIdx.x;
    if (i < N_NODES) { g_cnt_in[i] = 0; g_cnt_out[i] = 0; }
}

__global__ void degree_kernel(const int4* __restrict__ src4, const int4* __restrict__ dst4, int E4) {
    int i = blockIdx.x * blockDim.x + threadIdx.x;
    if (i >= E4) return;
    int4 s = src4[i], d = dst4[i];
    atomicAdd(&g_cnt_out[s.x], 1); atomicAdd(&g_cnt_out[s.y], 1);
    atomicAdd(&g_cnt_out[s.z], 1); atomicAdd(&g_cnt_out[s.w], 1);
    atomicAdd(&g_cnt_in[d.x], 1);  atomicAdd(&g_cnt_in[d.y], 1);
    atomicAdd(&g_cnt_in[d.z], 1);  atomicAdd(&g_cnt_in[d.w], 1);
}

// W1 and W2 -> fp16, one pass
__global__ void prep_weights_kernel(const float* __restrict__ W1, const float* __restrict__ W2) {
    int i = blockIdx.x * blockDim.x + threadIdx.x;
    if (i < IN_DIM * HID) g_w1h[i] = __float2half(W1[i]);
    else if (i < IN_DIM * HID + HID * OUT_DIM) g_w2h[i - IN_DIM * HID] = __float2half(W2[i - IN_DIM * HID]);
}

// ---------------- CSR build (shfl scans) ----------------
__global__ __launch_bounds__(1024) void scan1_kernel() {
    __shared__ int wsum[32];
    int tid = threadIdx.x, lane = tid & 31, wid = tid >> 5;
    int i = blockIdx.x * 1024 + tid;
    int v = (i < N_NODES) ? g_cnt_in[i] : 0;
    int x = v;
#pragma unroll
    for (int o = 1; o < 32; o <<= 1) {
        int t = __shfl_up_sync(0xffffffff, x, o);
        if (lane >= o) x += t;
    }
    if (lane == 31) wsum[wid] = x;
    __syncthreads();
    if (wid == 0) {
        int w = wsum[lane];
#pragma unroll
        for (int o = 1; o < 32; o <<= 1) {
            int t = __shfl_up_sync(0xffffffff, w, o);
            if (lane >= o) w += t;
        }
        wsum[lane] = w;
    }
    __syncthreads();
    int base = (wid > 0) ? wsum[wid - 1] : 0;
    x += base;
    if (i < N_NODES) g_incl[i] = x;
    if (tid == 1023) g_bsum[blockIdx.x] = x;
}

__global__ __launch_bounds__(128) void scan2_kernel() {
    __shared__ int wsum[4];
    int tid = threadIdx.x, lane = tid & 31, wid = tid >> 5;
    int v = (tid < NB_SCAN) ? g_bsum[tid] : 0;
    int x = v;
#pragma unroll
    for (int o = 1; o < 32; o <<= 1) {
        int t = __shfl_up_sync(0xffffffff, x, o);
        if (lane >= o) x += t;
    }
    if (lane == 31) wsum[wid] = x;
    __syncthreads();
    int base = 0;
#pragma unroll
    for (int w = 0; w < 4; w++) base += (w < wid) ? wsum[w] : 0;
    if (tid < NB_SCAN) g_boff[tid] = x + base - v;   // exclusive
}

__global__ void scan3_kernel() {
    int i = blockIdx.x * blockDim.x + threadIdx.x;
    if (i >= N_NODES) return;
    int boff = g_boff[i >> 10];
    int excl = g_incl[i] - g_cnt_in[i] + boff;
    g_row_off[i] = excl;
    g_cursor[i]  = excl;
    if (i == N_NODES - 1) g_row_off[N_NODES] = g_incl[i] + boff;
}

__global__ void scatter_kernel(const int4* __restrict__ src4, const int4* __restrict__ dst4, int E4) {
    int i = blockIdx.x * blockDim.x + threadIdx.x;
    if (i >= E4) return;
    int4 s = src4[i], d = dst4[i];
    g_csr_src[atomicAdd(&g_cursor[d.x], 1)] = s.x;
    g_csr_src[atomicAdd(&g_cursor[d.y], 1)] = s.y;
    g_csr_src[atomicAdd(&g_cursor[d.z], 1)] = s.z;
    g_csr_src[atomicAdd(&g_cursor[d.w], 1)] = s.w;
}

// ---------------------------------------------------------------------------
// GEMM1 (HMMA, A-prefetch): g_h1 = fp16((h @ W1) * deg_out^-1/2)
// ---------------------------------------------------------------------------
#define G1_SMEM (IN_DIM * 136 * 2)   // 69632 bytes
__global__ __launch_bounds__(256) void gemm1_kernel(const float* __restrict__ A) {
    extern __shared__ __half Bsh[];   // [256][136]
    const int tid = threadIdx.x;
    const int wid = tid >> 5, lane = tid & 31;
    const int m0 = blockIdx.x * 128 + wid * 16;

    {
        const uint4* srcr = reinterpret_cast<const uint4*>(g_w1h + (size_t)tid * HID);
        uint4* dstr = reinterpret_cast<uint4*>(Bsh + (size_t)tid * 136);
#pragma unroll
        for (int i = 0; i < 16; i++) dstr[i] = srcr[i];
    }
    __syncthreads();

    const int g = lane >> 2, tg = lane & 3;
    const int row0 = m0 + g, row1 = m0 + g + 8;
    const bool ok0 = row0 < N_NODES, ok1 = row1 < N_NODES;
    const float* pa0 = A + (size_t)(ok0 ? row0 : 0) * IN_DIM + tg * 2;
    const float* pa1 = A + (size_t)(ok1 ? row1 : 0) * IN_DIM + tg * 2;

    const int k_off = (lane & 7) + ((lane >> 3) & 1) * 8;
    const int n_off = (lane >> 4) * 8;

    float acc[16][4];
#pragma unroll
    for (int t = 0; t < 16; t++)
#pragma unroll
        for (int j = 0; j < 4; j++) acc[t][j] = 0.f;

    const float2 z2 = make_float2(0.f, 0.f);
    // prefetch k-tile 0
    float2 nf0 = ok0 ? *reinterpret_cast<const float2*>(pa0) : z2;
    float2 nf1 = ok1 ? *reinterpret_cast<const float2*>(pa1) : z2;
    float2 nf2 = ok0 ? *reinterpret_cast<const float2*>(pa0 + 8) : z2;
    float2 nf3 = ok1 ? *reinterpret_cast<const float2*>(pa1 + 8) : z2;

    for (int kt = 0; kt < 16; kt++) {
        uint32_t a0 = h2u(__floats2half2_rn(nf0.x, nf0.y));
        uint32_t a1 = h2u(__floats2half2_rn(nf1.x, nf1.y));
        uint32_t a2 = h2u(__floats2half2_rn(nf2.x, nf2.y));
        uint32_t a3 = h2u(__floats2half2_rn(nf3.x, nf3.y));

        if (kt < 15) {   // prefetch next k-tile while mma chain runs
            const int k1 = (kt + 1) * 16;
            nf0 = ok0 ? *reinterpret_cast<const float2*>(pa0 + k1) : z2;
            nf1 = ok1 ? *reinterpret_cast<const float2*>(pa1 + k1) : z2;
            nf2 = ok0 ? *reinterpret_cast<const float2*>(pa0 + k1 + 8) : z2;
            nf3 = ok1 ? *reinterpret_cast<const float2*>(pa1 + k1 + 8) : z2;
        }

        uint32_t base = smem_u32(Bsh + (size_t)(kt * 16 + k_off) * 136 + n_off);
#pragma unroll
        for (int p = 0; p < 8; p++) {
            uint32_t b0, b1, b2, b3;
            asm volatile("ldmatrix.sync.aligned.m8n8.x4.trans.shared.b16 {%0,%1,%2,%3}, [%4];"
                         : "=r"(b0), "=r"(b1), "=r"(b2), "=r"(b3)
                         : "r"(base + p * 32));
            mma16816(acc[2 * p],     a0, a1, a2, a3, b0, b1);
            mma16816(acc[2 * p + 1], a0, a1, a2, a3, b2, b3);
        }
    }

    float s0 = ok0 ? rsqrtf(fmaxf((float)g_cnt_out[row0], 1.f)) : 0.f;
    float s1 = ok1 ? rsqrtf(fmaxf((float)g_cnt_out[row1], 1.f)) : 0.f;
#pragma unroll
    for (int t = 0; t < 16; t++) {
        int col = t * 8 + tg * 2;
        if (ok0)
            *reinterpret_cast<__half2*>(g_h1 + (size_t)row0 * HID + col) =
                __floats2half2_rn(acc[t][0] * s0, acc[t][1] * s0);
        if (ok1)
            *reinterpret_cast<__half2*>(g_h1 + (size_t)row1 * HID + col) =
                __floats2half2_rn(acc[t][2] * s1, acc[t][3] * s1);
    }
}

// ---------------------------------------------------------------------------
// SpMM1 (pull, CSR, fp16 gather): TWO nodes per warp (16 lanes each).
// Lane owns 8 cols (uint4 = 8 half). Fused norm + bias + relu -> x1 fp16.
// ---------------------------------------------------------------------------
__global__ __launch_bounds__(256) void spmm1_csr_kernel(const float* __restrict__ b1) {
    int w = (blockIdx.x * blockDim.x + threadIdx.x) >> 5;
    int lane = threadIdx.x & 31;
    int hl = lane & 15;           // lane within half
    int n = w * 2 + (lane >> 4);  // each 16-lane half owns one node
    if (n >= N_NODES) return;     // N even -> whole warp exits together

    int start = g_row_off[n];
    int end   = g_row_off[n + 1];
    int deg   = end - start;
    int myit  = (deg + 15) >> 4;
    int oit   = __shfl_xor_sync(0xffffffffu, myit, 16);
    int maxit = max(myit, oit);

    float acc[8];
#pragma unroll
    for (int i = 0; i < 8; i++) acc[i] = 0.f;

    const int selbase = lane & 16;
    for (int it = 0; it < maxit; it++) {
        int j = start + it * 16 + hl;
        int s = (j < end) ? __ldg(&g_csr_src[j]) : 0;
        int cnt = min(16, deg - it * 16);   // may be <= 0 for this half
#pragma unroll 4
        for (int k = 0; k < 16; k++) {
            int sv = __shfl_sync(0xffffffffu, s, selbase | k);
            if (k < cnt) {
                uint4 pk = *reinterpret_cast<const uint4*>(g_h1 + (size_t)sv * HID + hl * 8);
                float2 f0 = __half22float2(*reinterpret_cast<__half2*>(&pk.x));
                float2 f1 = __half22float2(*reinterpret_cast<__half2*>(&pk.y));
                float2 f2 = __half22float2(*reinterpret_cast<__half2*>(&pk.z));
                float2 f3 = __half22float2(*reinterpret_cast<__half2*>(&pk.w));
                acc[0] += f0.x; acc[1] += f0.y; acc[2] += f1.x; acc[3] += f1.y;
                acc[4] += f2.x; acc[5] += f2.y; acc[6] += f3.x; acc[7] += f3.y;
            }
        }
    }

    float sc = rsqrtf(fmaxf((float)deg, 1.0f));
    float4 b0 = *reinterpret_cast<const float4*>(b1 + hl * 8);
    float4 b4 = *reinterpret_cast<const float4*>(b1 + hl * 8 + 4);
    float o0 = fmaxf(acc[0] * sc + b0.x, 0.f), o1 = fmaxf(acc[1] * sc + b0.y, 0.f);
    float o2 = fmaxf(acc[2] * sc + b0.z, 0.f), o3 = fmaxf(acc[3] * sc + b0.w, 0.f);
    float o4 = fmaxf(acc[4] * sc + b4.x, 0.f), o5 = fmaxf(acc[5] * sc + b4.y, 0.f);
    float o6 = fmaxf(acc[6] * sc + b4.z, 0.f), o7 = fmaxf(acc[7] * sc + b4.w, 0.f);
    uint4 pk = make_uint4(h2u(__floats2half2_rn(o0, o1)), h2u(__floats2half2_rn(o2, o3)),
                          h2u(__floats2half2_rn(o4, o5)), h2u(__floats2half2_rn(o6, o7)));
    *reinterpret_cast<uint4*>(g_x1h + (size_t)n * HID + hl * 8) = pk;
}

// ---------------------------------------------------------------------------
// GEMM2 (HMMA): g_x2 = fp16((x1 @ W2) * deg_out^-1/2)
// ---------------------------------------------------------------------------
#define G2_NPAD 56
__global__ __launch_bounds__(256) void gemm2_kernel() {
    __shared__ __half Wsh[HID * G2_NPAD];   // 14336 B
    const int tid = threadIdx.x;
    const int wid = tid >> 5, lane = tid & 31;
    const int m0 = blockIdx.x * 128 + wid * 16;

    for (int i = tid; i < HID * G2_NPAD; i += 256) {
        int r = i / G2_NPAD, c = i % G2_NPAD;
        Wsh[i] = (c < OUT_DIM) ? g_w2h[r * OUT_DIM + c] : __float2half(0.f);
    }
    __syncthreads();

    const int g = lane >> 2, tg = lane & 3;
    const int row0 = m0 + g, row1 = m0 + g + 8;
    const bool ok0 = row0 < N_NODES, ok1 = row1 < N_NODES;
    const __half* px0 = g_x1h + (size_t)(ok0 ? row0 : 0) * HID + tg * 2;
    const __half* px1 = g_x1h + (size_t)(ok1 ? row1 : 0) * HID + tg * 2;

    const int k_off = (lane & 7) + ((lane >> 3) & 1) * 8;
    const int n_off = (lane >> 4) * 8;

    float acc[6][4];
#pragma unroll
    for (int t = 0; t < 6; t++)
#pragma unroll
        for (int j = 0; j < 4; j++) acc[t][j] = 0.f;

    for (int kt = 0; kt < 8; kt++) {
        const int k0 = kt * 16;
        uint32_t a0 = ok0 ? *reinterpret_cast<const uint32_t*>(px0 + k0) : 0u;
        uint32_t a1 = ok1 ? *reinterpret_cast<const uint32_t*>(px1 + k0) : 0u;
        uint32_t a2 = ok0 ? *reinterpret_cast<const uint32_t*>(px0 + k0 + 8) : 0u;
        uint32_t a3 = ok1 ? *reinterpret_cast<const uint32_t*>(px1 + k0 + 8) : 0u;

        uint32_t base = smem_u32(Wsh + (size_t)(k0 + k_off) * G2_NPAD + n_off);
#pragma unroll
        for (int p = 0; p < 3; p++) {
            uint32_t b0, b1, b2, b3;
            asm volatile("ldmatrix.sync.aligned.m8n8.x4.trans.shared.b16 {%0,%1,%2,%3}, [%4];"
                         : "=r"(b0), "=r"(b1), "=r"(b2), "=r"(b3)
                         : "r"(base + p * 32));
            mma16816(acc[2 * p],     a0, a1, a2, a3, b0, b1);
            mma16816(acc[2 * p + 1], a0, a1, a2, a3, b2, b3);
        }
    }

    float s0 = ok0 ? rsqrtf(fmaxf((float)g_cnt_out[row0], 1.f)) : 0.f;
    float s1 = ok1 ? rsqrtf(fmaxf((float)g_cnt_out[row1], 1.f)) : 0.f;
#pragma unroll
    for (int t = 0; t < 5; t++) {
        int col = t * 8 + tg * 2;
        if (ok0)
            *reinterpret_cast<__half2*>(g_x2 + (size_t)row0 * OUT_DIM + col) =
                __floats2half2_rn(acc[t][0] * s0, acc[t][1] * s0);
        if (ok1)
            *reinterpret_cast<__half2*>(g_x2 + (size_t)row1 * OUT_DIM + col) =
                __floats2half2_rn(acc[t][2] * s1, acc[t][3] * s1);
    }
}

// ---------------------------------------------------------------------------
// SpMM2 (pull, CSR, fp16 gather) + fused norm + bias + log_softmax.
// ---------------------------------------------------------------------------
__global__ __launch_bounds__(256) void spmm2_csr_kernel(float* __restrict__ out,
                                                        const float* __restrict__ b2) {
    int n = (blockIdx.x * blockDim.x + threadIdx.x) >> 5;
    if (n >= N_NODES) return;
    int lane = threadIdx.x & 31;
    int half = lane >> 4;
    int hl   = lane & 15;
    bool act = hl < (OUT_DIM / 4);
    int start = g_row_off[n];
    int end   = g_row_off[n + 1];

    float ax = 0.f, ay = 0.f, az = 0.f, aw = 0.f;
    for (int j = start; j < end; j += 32) {
        int s = 0;
        if (j + lane < end) s = __ldg(&g_csr_src[j + lane]);
        int cnt = min(32, end - j);
        if (cnt == 32) {
#pragma unroll 4
            for (int k = 0; k < 32; k += 2) {
                int sv = __shfl_sync(0xffffffff, s, k + half);
                if (act) {
                    uint2 pk = *reinterpret_cast<const uint2*>(g_x2 + (size_t)sv * OUT_DIM + hl * 4);
                    float2 f0 = __half22float2(*reinterpret_cast<__half2*>(&pk.x));
                    float2 f1 = __half22float2(*reinterpret_cast<__half2*>(&pk.y));
                    ax += f0.x; ay += f0.y; az += f1.x; aw += f1.y;
                }
            }
        } else {
            for (int k = 0; k < cnt; k += 2) {
                int idx = k + half;
                bool ok = act && (idx < cnt);
                int sv = __shfl_sync(0xffffffff, s, idx < cnt ? idx : k);
                if (ok) {
                    uint2 pk = *reinterpret_cast<const uint2*>(g_x2 + (size_t)sv * OUT_DIM + hl * 4);
                    float2 f0 = __half22float2(*reinterpret_cast<__half2*>(&pk.x));
                    float2 f1 = __half22float2(*reinterpret_cast<__half2*>(&pk.y));
                    ax += f0.x; ay += f0.y; az += f1.x; aw += f1.y;
                }
            }
        }
    }
    ax += __shfl_down_sync(0xffffffff, ax, 16);
    ay += __shfl_down_sync(0xffffffff, ay, 16);
    az += __shfl_down_sync(0xffffffff, az, 16);
    aw += __shfl_down_sync(0xffffffff, aw, 16);

    bool fin = (lane < OUT_DIM / 4);
    float sc = rsqrtf(fmaxf((float)(end - start), 1.0f));
    float4 x = make_float4(-FLT_MAX, -FLT_MAX, -FLT_MAX, -FLT_MAX);
    if (fin) {
        float4 bb = *reinterpret_cast<const float4*>(b2 + lane * 4);
        x.x = ax * sc + bb.x;
        x.y = ay * sc + bb.y;
        x.z = az * sc + bb.z;
        x.w = aw * sc + bb.w;
    }

    float m = fmaxf(fmaxf(x.x, x.y), fmaxf(x.z, x.w));
#pragma unroll
    for (int o = 16; o > 0; o >>= 1) m = fmaxf(m, __shfl_xor_sync(0xffffffff, m, o));

    float se = 0.f;
    if (fin) se = expf(x.x - m) + expf(x.y - m) + expf(x.z - m) + expf(x.w - m);
#pragma unroll
    for (int o = 16; o > 0; o >>= 1) se += __shfl_xor_sync(0xffffffff, se, o);

    float lse = m + logf(se);
    if (fin) {
        float4 r = make_float4(x.x - lse, x.y - lse, x.z - lse, x.w - lse);
        *reinterpret_cast<float4*>(out + (size_t)n * OUT_DIM + lane * 4) = r;
    }
}

// ---------------------------------------------------------------------------
extern "C" void kernel_launch(void* const* d_in, const int* in_sizes, int n_in,
                              void* d_out, int out_size) {
    const float* h  = (const float*)d_in[0];
    const float* W1 = (const float*)d_in[1];
    const float* b1 = (const float*)d_in[2];
    const float* W2 = (const float*)d_in[3];
    const float* b2 = (const float*)d_in[4];
    const int* src  = (const int*)d_in[5];
    const int* dst  = (const int*)d_in[6];
    float* out      = (float*)d_out;
    const int E     = in_sizes[5];
    const int E4    = E / 4;

    cudaFuncSetAttribute(gemm1_kernel, cudaFuncAttributeMaxDynamicSharedMemorySize, G1_SMEM);

    const int PREP_N = IN_DIM * HID + HID * OUT_DIM;
    zero_counts_kernel<<<(N_NODES + 255) / 256, 256>>>();                                    // 1
    degree_kernel<<<(E4 + 255) / 256, 256>>>((const int4*)src, (const int4*)dst, E4);        // 2
    prep_weights_kernel<<<(PREP_N + 255) / 256, 256>>>(W1, W2);                              // 3
    gemm1_kernel<<<(N_NODES + 127) / 128, 256, G1_SMEM>>>(h);                                // 4 (profiled)
    scan1_kernel<<<NB_SCAN, 1024>>>();                                                       // 5
    scan2_kernel<<<1, 128>>>();                                                              // 6
    scan3_kernel<<<(N_NODES + 255) / 256, 256>>>();                                          // 7
    scatter_kernel<<<(E4 + 255) / 256, 256>>>((const int4*)src, (const int4*)dst, E4);       // 8
    spmm1_csr_kernel<<<(N_NODES / 2 * 32 + 255) / 256, 256>>>(b1);                           // 9
    gemm2_kernel<<<(N_NODES + 127) / 128, 256>>>();                                          // 10
    spmm2_csr_kernel<<<(N_NODES * 32 + 255) / 256, 256>>>(out, b2);                          // 11
}

// round 13
// speedup vs baseline: 1.0714x; 1.0714x over previous
#include <cuda_runtime.h>
#include <cuda_fp16.h>
#include <math.h>
#include <float.h>
#include <stdint.h>

#define N_NODES 100000
#define IN_DIM  256
#define HID     128
#define OUT_DIM 40
#define E_MAX   3200000
#define NB_SCAN ((N_NODES + 1023) / 1024)   // 98

typedef unsigned long long u64;

// ---------------- scratch (device globals, allocation-free) ----------------
__device__ int   g_cnt_in[N_NODES];
__device__ int   g_cnt_out[N_NODES];
__device__ int   g_incl[N_NODES];
__device__ int   g_bsum[NB_SCAN];
__device__ int   g_boff[NB_SCAN];
__device__ int   g_row_off[N_NODES + 1];
__device__ int   g_cursor[N_NODES];
__device__ int   g_csr_src[E_MAX];
__device__ __half g_w1h[(size_t)IN_DIM * HID];     // W1 fp16 [k][n]
__device__ __half g_w2h[(size_t)HID * OUT_DIM];    // W2 fp16 [k][n]
__device__ __half g_h1[(size_t)N_NODES * HID];     // h1 fp16 (layer-1 pre-agg)
__device__ __half g_x1h[(size_t)N_NODES * HID];    // x1 fp16 (gemm2 input)
__device__ __half g_x2[(size_t)N_NODES * OUT_DIM]; // x2 fp16 (layer-2 pre-agg)

// ---------------- helpers ----------------
__device__ __forceinline__ uint32_t h2u(__half2 h) {
    uint32_t u;
    memcpy(&u, &h, 4);
    return u;
}
__device__ __forceinline__ uint32_t smem_u32(const void* p) {
    uint32_t a;
    asm("{ .reg .u64 t; cvta.to.shared.u64 t, %1; cvt.u32.u64 %0, t; }" : "=r"(a) : "l"(p));
    return a;
}
// mma.sync m16n8k16 f16 x f16 -> f32
__device__ __forceinline__ void mma16816(float* c, uint32_t a0, uint32_t a1, uint32_t a2,
                                         uint32_t a3, uint32_t b0, uint32_t b1) {
    asm volatile("mma.sync.aligned.m16n8k16.row.col.f32.f16.f16.f32 "
                 "{%0,%1,%2,%3}, {%4,%5,%6,%7}, {%8,%9}, {%0,%1,%2,%3};"
                 : "+f"(c[0]), "+f"(c[1]), "+f"(c[2]), "+f"(c[3])
                 : "r"(a0), "r"(a1), "r"(a2), "r"(a3), "r"(b0), "r"(b1));
}

// ---------------------------------------------------------------------------
__global__ void zero_counts_kernel() {
    int i = blockIdx.x * blockDim.x + threadIdx.x;
    if (i < N_NODES) { g_cnt_in[i] = 0; g_cnt_out[i] = 0; }
}

__global__ void degree_kernel(const int4* __restrict__ src4, const int4* __restrict__ dst4, int E4) {
    int i = blockIdx.x * blockDim.x + threadIdx.x;
    if (i >= E4) return;
    int4 s = src4[i], d = dst4[i];
    atomicAdd(&g_cnt_out[s.x], 1); atomicAdd(&g_cnt_out[s.y], 1);
    atomicAdd(&g_cnt_out[s.z], 1); atomicAdd(&g_cnt_out[s.w], 1);
    atomicAdd(&g_cnt_in[d.x], 1);  atomicAdd(&g_cnt_in[d.y], 1);
    atomicAdd(&g_cnt_in[d.z], 1);  atomicAdd(&g_cnt_in[d.w], 1);
}

// W1 and W2 -> fp16, one pass
__global__ void prep_weights_kernel(const float* __restrict__ W1, const float* __restrict__ W2) {
    int i = blockIdx.x * blockDim.x + threadIdx.x;
    if (i < IN_DIM * HID) g_w1h[i] = __float2half(W1[i]);
    else if (i < IN_DIM * HID + HID * OUT_DIM) g_w2h[i - IN_DIM * HID] = __float2half(W2[i - IN_DIM * HID]);
}

// ---------------- CSR build (shfl scans) ----------------
__global__ __launch_bounds__(1024) void scan1_kernel() {
    __shared__ int wsum[32];
    int tid = threadIdx.x, lane = tid & 31, wid = tid >> 5;
    int i = blockIdx.x * 1024 + tid;
    int v = (i < N_NODES) ? g_cnt_in[i] : 0;
    int x = v;
#pragma unroll
    for (int o = 1; o < 32; o <<= 1) {
        int t = __shfl_up_sync(0xffffffff, x, o);
        if (lane >= o) x += t;
    }
    if (lane == 31) wsum[wid] = x;
    __syncthreads();
    if (wid == 0) {
        int w = wsum[lane];
#pragma unroll
        for (int o = 1; o < 32; o <<= 1) {
            int t = __shfl_up_sync(0xffffffff, w, o);
            if (lane >= o) w += t;
        }
        wsum[lane] = w;
    }
    __syncthreads();
    int base = (wid > 0) ? wsum[wid - 1] : 0;
    x += base;
    if (i < N_NODES) g_incl[i] = x;
    if (tid == 1023) g_bsum[blockIdx.x] = x;
}

__global__ __launch_bounds__(128) void scan2_kernel() {
    __shared__ int wsum[4];
    int tid = threadIdx.x, lane = tid & 31, wid = tid >> 5;
    int v = (tid < NB_SCAN) ? g_bsum[tid] : 0;
    int x = v;
#pragma unroll
    for (int o = 1; o < 32; o <<= 1) {
        int t = __shfl_up_sync(0xffffffff, x, o);
        if (lane >= o) x += t;
    }
    if (lane == 31) wsum[wid] = x;
    __syncthreads();
    int base = 0;
#pragma unroll
    for (int w = 0; w < 4; w++) base += (w < wid) ? wsum[w] : 0;
    if (tid < NB_SCAN) g_boff[tid] = x + base - v;   // exclusive
}

__global__ void scan3_kernel() {
    int i = blockIdx.x * blockDim.x + threadIdx.x;
    if (i >= N_NODES) return;
    int boff = g_boff[i >> 10];
    int excl = g_incl[i] - g_cnt_in[i] + boff;
    g_row_off[i] = excl;
    g_cursor[i]  = excl;
    if (i == N_NODES - 1) g_row_off[N_NODES] = g_incl[i] + boff;
}

__global__ void scatter_kernel(const int4* __restrict__ src4, const int4* __restrict__ dst4, int E4) {
    int i = blockIdx.x * blockDim.x + threadIdx.x;
    if (i >= E4) return;
    int4 s = src4[i], d = dst4[i];
    g_csr_src[atomicAdd(&g_cursor[d.x], 1)] = s.x;
    g_csr_src[atomicAdd(&g_cursor[d.y], 1)] = s.y;
    g_csr_src[atomicAdd(&g_cursor[d.z], 1)] = s.z;
    g_csr_src[atomicAdd(&g_cursor[d.w], 1)] = s.w;
}

// ---------------------------------------------------------------------------
// GEMM1 (HMMA, reg-lean A-prefetch): g_h1 = fp16((h @ W1) * deg_out^-1/2)
// Prefetched A values converted to half2 at load time (4 uint regs, not 8 f32);
// __launch_bounds__(256,2) pins regs <= 128 so 2 CTAs/SM stay resident.
// ---------------------------------------------------------------------------
#define G1_SMEM (IN_DIM * 136 * 2)   // 69632 bytes
__global__ __launch_bounds__(256, 2) void gemm1_kernel(const float* __restrict__ A) {
    extern __shared__ __half Bsh[];   // [256][136]
    const int tid = threadIdx.x;
    const int wid = tid >> 5, lane = tid & 31;
    const int m0 = blockIdx.x * 128 + wid * 16;

    {
        const uint4* srcr = reinterpret_cast<const uint4*>(g_w1h + (size_t)tid * HID);
        uint4* dstr = reinterpret_cast<uint4*>(Bsh + (size_t)tid * 136);
#pragma unroll
        for (int i = 0; i < 16; i++) dstr[i] = srcr[i];
    }
    __syncthreads();

    const int g = lane >> 2, tg = lane & 3;
    const int row0 = m0 + g, row1 = m0 + g + 8;
    const bool ok0 = row0 < N_NODES, ok1 = row1 < N_NODES;
    const float* pa0 = A + (size_t)(ok0 ? row0 : 0) * IN_DIM + tg * 2;
    const float* pa1 = A + (size_t)(ok1 ? row1 : 0) * IN_DIM + tg * 2;

    const int k_off = (lane & 7) + ((lane >> 3) & 1) * 8;
    const int n_off = (lane >> 4) * 8;

    float acc[16][4];
#pragma unroll
    for (int t = 0; t < 16; t++)
#pragma unroll
        for (int j = 0; j < 4; j++) acc[t][j] = 0.f;

    const float2 z2 = make_float2(0.f, 0.f);
    float2 f;
    // prefetch tile 0, converting immediately (4 uint regs live)
    f = ok0 ? *reinterpret_cast<const float2*>(pa0) : z2;
    uint32_t na0 = h2u(__floats2half2_rn(f.x, f.y));
    f = ok1 ? *reinterpret_cast<const float2*>(pa1) : z2;
    uint32_t na1 = h2u(__floats2half2_rn(f.x, f.y));
    f = ok0 ? *reinterpret_cast<const float2*>(pa0 + 8) : z2;
    uint32_t na2 = h2u(__floats2half2_rn(f.x, f.y));
    f = ok1 ? *reinterpret_cast<const float2*>(pa1 + 8) : z2;
    uint32_t na3 = h2u(__floats2half2_rn(f.x, f.y));

    for (int kt = 0; kt < 16; kt++) {
        uint32_t a0 = na0, a1 = na1, a2 = na2, a3 = na3;
        if (kt < 15) {
            const int k1 = (kt + 1) * 16;
            f = ok0 ? *reinterpret_cast<const float2*>(pa0 + k1) : z2;
            na0 = h2u(__floats2half2_rn(f.x, f.y));
            f = ok1 ? *reinterpret_cast<const float2*>(pa1 + k1) : z2;
            na1 = h2u(__floats2half2_rn(f.x, f.y));
            f = ok0 ? *reinterpret_cast<const float2*>(pa0 + k1 + 8) : z2;
            na2 = h2u(__floats2half2_rn(f.x, f.y));
            f = ok1 ? *reinterpret_cast<const float2*>(pa1 + k1 + 8) : z2;
            na3 = h2u(__floats2half2_rn(f.x, f.y));
        }

        uint32_t base = smem_u32(Bsh + (size_t)(kt * 16 + k_off) * 136 + n_off);
#pragma unroll
        for (int p = 0; p < 8; p++) {
            uint32_t b0, b1, b2, b3;
            asm volatile("ldmatrix.sync.aligned.m8n8.x4.trans.shared.b16 {%0,%1,%2,%3}, [%4];"
                         : "=r"(b0), "=r"(b1), "=r"(b2), "=r"(b3)
                         : "r"(base + p * 32));
            mma16816(acc[2 * p],     a0, a1, a2, a3, b0, b1);
            mma16816(acc[2 * p + 1], a0, a1, a2, a3, b2, b3);
        }
    }

    float s0 = ok0 ? rsqrtf(fmaxf((float)g_cnt_out[row0], 1.f)) : 0.f;
    float s1 = ok1 ? rsqrtf(fmaxf((float)g_cnt_out[row1], 1.f)) : 0.f;
#pragma unroll
    for (int t = 0; t < 16; t++) {
        int col = t * 8 + tg * 2;
        if (ok0)
            *reinterpret_cast<__half2*>(g_h1 + (size_t)row0 * HID + col) =
                __floats2half2_rn(acc[t][0] * s0, acc[t][1] * s0);
        if (ok1)
            *reinterpret_cast<__half2*>(g_h1 + (size_t)row1 * HID + col) =
                __floats2half2_rn(acc[t][2] * s1, acc[t][3] * s1);
    }
}

// ---------------------------------------------------------------------------
// SpMM1 (pull, CSR, fp16 gather): warp per dst node (round-11 version),
// fused norm+bias+relu -> x1 fp16.
// ---------------------------------------------------------------------------
__global__ __launch_bounds__(256) void spmm1_csr_kernel(const float* __restrict__ b1) {
    int n = (blockIdx.x * blockDim.x + threadIdx.x) >> 5;
    if (n >= N_NODES) return;
    int lane = threadIdx.x & 31;
    int start = g_row_off[n];
    int end   = g_row_off[n + 1];

    float ax = 0.f, ay = 0.f, az = 0.f, aw = 0.f;
    for (int j = start; j < end; j += 32) {
        int s = 0;
        if (j + lane < end) s = __ldg(&g_csr_src[j + lane]);
        int cnt = min(32, end - j);
        if (cnt == 32) {
#pragma unroll 4
            for (int k = 0; k < 32; k++) {
                int sv = __shfl_sync(0xffffffff, s, k);
                uint2 pk = *reinterpret_cast<const uint2*>(g_h1 + (size_t)sv * HID + lane * 4);
                float2 f0 = __half22float2(*reinterpret_cast<__half2*>(&pk.x));
                float2 f1 = __half22float2(*reinterpret_cast<__half2*>(&pk.y));
                ax += f0.x; ay += f0.y; az += f1.x; aw += f1.y;
            }
        } else {
            for (int k = 0; k < cnt; k++) {
                int sv = __shfl_sync(0xffffffff, s, k);
                uint2 pk = *reinterpret_cast<const uint2*>(g_h1 + (size_t)sv * HID + lane * 4);
                float2 f0 = __half22float2(*reinterpret_cast<__half2*>(&pk.x));
                float2 f1 = __half22float2(*reinterpret_cast<__half2*>(&pk.y));
                ax += f0.x; ay += f0.y; az += f1.x; aw += f1.y;
            }
        }
    }

    float sc = rsqrtf(fmaxf((float)(end - start), 1.0f));
    float4 bb = *reinterpret_cast<const float4*>(b1 + lane * 4);
    float ox = fmaxf(ax * sc + bb.x, 0.f);
    float oy = fmaxf(ay * sc + bb.y, 0.f);
    float oz = fmaxf(az * sc + bb.z, 0.f);
    float ow = fmaxf(aw * sc + bb.w, 0.f);
    uint2 pk = make_uint2(h2u(__floats2half2_rn(ox, oy)), h2u(__floats2half2_rn(oz, ow)));
    *reinterpret_cast<uint2*>(g_x1h + (size_t)n * HID + lane * 4) = pk;
}

// ---------------------------------------------------------------------------
// GEMM2 (HMMA): g_x2 = fp16((x1 @ W2) * deg_out^-1/2)
// ---------------------------------------------------------------------------
#define G2_NPAD 56
__global__ __launch_bounds__(256) void gemm2_kernel() {
    __shared__ __half Wsh[HID * G2_NPAD];   // 14336 B
    const int tid = threadIdx.x;
    const int wid = tid >> 5, lane = tid & 31;
    const int m0 = blockIdx.x * 128 + wid * 16;

    for (int i = tid; i < HID * G2_NPAD; i += 256) {
        int r = i / G2_NPAD, c = i % G2_NPAD;
        Wsh[i] = (c < OUT_DIM) ? g_w2h[r * OUT_DIM + c] : __float2half(0.f);
    }
    __syncthreads();

    const int g = lane >> 2, tg = lane & 3;
    const int row0 = m0 + g, row1 = m0 + g + 8;
    const bool ok0 = row0 < N_NODES, ok1 = row1 < N_NODES;
    const __half* px0 = g_x1h + (size_t)(ok0 ? row0 : 0) * HID + tg * 2;
    const __half* px1 = g_x1h + (size_t)(ok1 ? row1 : 0) * HID + tg * 2;

    const int k_off = (lane & 7) + ((lane >> 3) & 1) * 8;
    const int n_off = (lane >> 4) * 8;

    float acc[6][4];
#pragma unroll
    for (int t = 0; t < 6; t++)
#pragma unroll
        for (int j = 0; j < 4; j++) acc[t][j] = 0.f;

    for (int kt = 0; kt < 8; kt++) {
        const int k0 = kt * 16;
        uint32_t a0 = ok0 ? *reinterpret_cast<const uint32_t*>(px0 + k0) : 0u;
        uint32_t a1 = ok1 ? *reinterpret_cast<const uint32_t*>(px1 + k0) : 0u;
        uint32_t a2 = ok0 ? *reinterpret_cast<const uint32_t*>(px0 + k0 + 8) : 0u;
        uint32_t a3 = ok1 ? *reinterpret_cast<const uint32_t*>(px1 + k0 + 8) : 0u;

        uint32_t base = smem_u32(Wsh + (size_t)(k0 + k_off) * G2_NPAD + n_off);
#pragma unroll
        for (int p = 0; p < 3; p++) {
            uint32_t b0, b1, b2, b3;
            asm volatile("ldmatrix.sync.aligned.m8n8.x4.trans.shared.b16 {%0,%1,%2,%3}, [%4];"
                         : "=r"(b0), "=r"(b1), "=r"(b2), "=r"(b3)
                         : "r"(base + p * 32));
            mma16816(acc[2 * p],     a0, a1, a2, a3, b0, b1);
            mma16816(acc[2 * p + 1], a0, a1, a2, a3, b2, b3);
        }
    }

    float s0 = ok0 ? rsqrtf(fmaxf((float)g_cnt_out[row0], 1.f)) : 0.f;
    float s1 = ok1 ? rsqrtf(fmaxf((float)g_cnt_out[row1], 1.f)) : 0.f;
#pragma unroll
    for (int t = 0; t < 5; t++) {
        int col = t * 8 + tg * 2;
        if (ok0)
            *reinterpret_cast<__half2*>(g_x2 + (size_t)row0 * OUT_DIM + col) =
                __floats2half2_rn(acc[t][0] * s0, acc[t][1] * s0);
        if (ok1)
            *reinterpret_cast<__half2*>(g_x2 + (size_t)row1 * OUT_DIM + col) =
                __floats2half2_rn(acc[t][2] * s1, acc[t][3] * s1);
    }
}

// ---------------------------------------------------------------------------
// SpMM2 (pull, CSR, fp16 gather) + fused norm + bias + log_softmax.
// ---------------------------------------------------------------------------
__global__ __launch_bounds__(256) void spmm2_csr_kernel(float* __restrict__ out,
                                                        const float* __restrict__ b2) {
    int n = (blockIdx.x * blockDim.x + threadIdx.x) >> 5;
    if (n >= N_NODES) return;
    int lane = threadIdx.x & 31;
    int half = lane >> 4;
    int hl   = lane & 15;
    bool act = hl < (OUT_DIM / 4);
    int start = g_row_off[n];
    int end   = g_row_off[n + 1];

    float ax = 0.f, ay = 0.f, az = 0.f, aw = 0.f;
    for (int j = start; j < end; j += 32) {
        int s = 0;
        if (j + lane < end) s = __ldg(&g_csr_src[j + lane]);
        int cnt = min(32, end - j);
        if (cnt == 32) {
#pragma unroll 4
            for (int k = 0; k < 32; k += 2) {
                int sv = __shfl_sync(0xffffffff, s, k + half);
                if (act) {
                    uint2 pk = *reinterpret_cast<const uint2*>(g_x2 + (size_t)sv * OUT_DIM + hl * 4);
                    float2 f0 = __half22float2(*reinterpret_cast<__half2*>(&pk.x));
                    float2 f1 = __half22float2(*reinterpret_cast<__half2*>(&pk.y));
                    ax += f0.x; ay += f0.y; az += f1.x; aw += f1.y;
                }
            }
        } else {
            for (int k = 0; k < cnt; k += 2) {
                int idx = k + half;
                bool ok = act && (idx < cnt);
                int sv = __shfl_sync(0xffffffff, s, idx < cnt ? idx : k);
                if (ok) {
                    uint2 pk = *reinterpret_cast<const uint2*>(g_x2 + (size_t)sv * OUT_DIM + hl * 4);
                    float2 f0 = __half22float2(*reinterpret_cast<__half2*>(&pk.x));
                    float2 f1 = __half22float2(*reinterpret_cast<__half2*>(&pk.y));
                    ax += f0.x; ay += f0.y; az += f1.x; aw += f1.y;
                }
            }
        }
    }
    ax += __shfl_down_sync(0xffffffff, ax, 16);
    ay += __shfl_down_sync(0xffffffff, ay, 16);
    az += __shfl_down_sync(0xffffffff, az, 16);
    aw += __shfl_down_sync(0xffffffff, aw, 16);

    bool fin = (lane < OUT_DIM / 4);
    float sc = rsqrtf(fmaxf((float)(end - start), 1.0f));
    float4 x = make_float4(-FLT_MAX, -FLT_MAX, -FLT_MAX, -FLT_MAX);
    if (fin) {
        float4 bb = *reinterpret_cast<const float4*>(b2 + lane * 4);
        x.x = ax * sc + bb.x;
        x.y = ay * sc + bb.y;
        x.z = az * sc + bb.z;
        x.w = aw * sc + bb.w;
    }

    float m = fmaxf(fmaxf(x.x, x.y), fmaxf(x.z, x.w));
#pragma unroll
    for (int o = 16; o > 0; o >>= 1) m = fmaxf(m, __shfl_xor_sync(0xffffffff, m, o));

    float se = 0.f;
    if (fin) se = expf(x.x - m) + expf(x.y - m) + expf(x.z - m) + expf(x.w - m);
#pragma unroll
    for (int o = 16; o > 0; o >>= 1) se += __shfl_xor_sync(0xffffffff, se, o);

    float lse = m + logf(se);
    if (fin) {
        float4 r = make_float4(x.x - lse, x.y - lse, x.z - lse, x.w - lse);
        *reinterpret_cast<float4*>(out + (size_t)n * OUT_DIM + lane * 4) = r;
    }
}

// ---------------------------------------------------------------------------
extern "C" void kernel_launch(void* const* d_in, const int* in_sizes, int n_in,
                              void* d_out, int out_size) {
    const float* h  = (const float*)d_in[0];
    const float* W1 = (const float*)d_in[1];
    const float* b1 = (const float*)d_in[2];
    const float* W2 = (const float*)d_in[3];
    const float* b2 = (const float*)d_in[4];
    const int* src  = (const int*)d_in[5];
    const int* dst  = (const int*)d_in[6];
    float* out      = (float*)d_out;
    const int E     = in_sizes[5];
    const int E4    = E / 4;

    cudaFuncSetAttribute(gemm1_kernel, cudaFuncAttributeMaxDynamicSharedMemorySize, G1_SMEM);

    const int PREP_N = IN_DIM * HID + HID * OUT_DIM;
    zero_counts_kernel<<<(N_NODES + 255) / 256, 256>>>();                                    // 1
    degree_kernel<<<(E4 + 255) / 256, 256>>>((const int4*)src, (const int4*)dst, E4);        // 2
    prep_weights_kernel<<<(PREP_N + 255) / 256, 256>>>(W1, W2);                              // 3
    gemm1_kernel<<<(N_NODES + 127) / 128, 256, G1_SMEM>>>(h);                                // 4 (profiled)
    scan1_kernel<<<NB_SCAN, 1024>>>();                                                       // 5
    scan2_kernel<<<1, 128>>>();                                                              // 6
    scan3_kernel<<<(N_NODES + 255) / 256, 256>>>();                                          // 7
    scatter_kernel<<<(E4 + 255) / 256, 256>>>((const int4*)src, (const int4*)dst, E4);       // 8
    spmm1_csr_kernel<<<(N_NODES * 32 + 255) / 256, 256>>>(b1);                               // 9
    gemm2_kernel<<<(N_NODES + 127) / 128, 256>>>();                                          // 10
    spmm2_csr_kernel<<<(N_NODES * 32 + 255) / 256, 256>>>(out, b2);                          // 11
}

// round 14
// speedup vs baseline: 1.1115x; 1.0374x over previous
#include <cuda_runtime.h>
#include <cuda_fp16.h>
#include <math.h>
#include <float.h>
#include <stdint.h>

#define N_NODES 100000
#define IN_DIM  256
#define HID     128
#define OUT_DIM 40
#define E_MAX   3200000
#define NB_SCAN ((N_NODES + 1023) / 1024)   // 98

typedef unsigned long long u64;

// ---------------- scratch (device globals, allocation-free) ----------------
__device__ int   g_cnt_in[N_NODES];
__device__ int   g_cnt_out[N_NODES];
__device__ int   g_incl[N_NODES];
__device__ int   g_bsum[NB_SCAN];
__device__ int   g_boff[NB_SCAN];
__device__ int   g_row_off[N_NODES + 1];
__device__ int   g_cursor[N_NODES];
__device__ int   g_csr_src[E_MAX];
__device__ __half g_w1h[(size_t)IN_DIM * HID];     // W1 fp16 [k][n]
__device__ __half g_w2h[(size_t)HID * OUT_DIM];    // W2 fp16 [k][n]
__device__ __half g_h1[(size_t)N_NODES * HID];     // h1 fp16 (layer-1 pre-agg)
__device__ __half g_x1h[(size_t)N_NODES * HID];    // x1 fp16 (gemm2 input)
__device__ __half g_x2[(size_t)N_NODES * OUT_DIM]; // x2 fp16 (layer-2 pre-agg)

// ---------------- helpers ----------------
__device__ __forceinline__ uint32_t h2u(__half2 h) {
    uint32_t u;
    memcpy(&u, &h, 4);
    return u;
}
__device__ __forceinline__ uint32_t smem_u32(const void* p) {
    uint32_t a;
    asm("{ .reg .u64 t; cvta.to.shared.u64 t, %1; cvt.u32.u64 %0, t; }" : "=r"(a) : "l"(p));
    return a;
}
// mma.sync m16n8k16 f16 x f16 -> f32
__device__ __forceinline__ void mma16816(float* c, uint32_t a0, uint32_t a1, uint32_t a2,
                                         uint32_t a3, uint32_t b0, uint32_t b1) {
    asm volatile("mma.sync.aligned.m16n8k16.row.col.f32.f16.f16.f32 "
                 "{%0,%1,%2,%3}, {%4,%5,%6,%7}, {%8,%9}, {%0,%1,%2,%3};"
                 : "+f"(c[0]), "+f"(c[1]), "+f"(c[2]), "+f"(c[3])
                 : "r"(a0), "r"(a1), "r"(a2), "r"(a3), "r"(b0), "r"(b1));
}

// ---------------------------------------------------------------------------
__global__ void zero_counts_kernel() {
    int i = blockIdx.x * blockDim.x + threadIdx.x;
    if (i < N_NODES) { g_cnt_in[i] = 0; g_cnt_out[i] = 0; }
}

__global__ void degree_kernel(const int4* __restrict__ src4, const int4* __restrict__ dst4, int E4) {
    int i = blockIdx.x * blockDim.x + threadIdx.x;
    if (i >= E4) return;
    int4 s = src4[i], d = dst4[i];
    atomicAdd(&g_cnt_out[s.x], 1); atomicAdd(&g_cnt_out[s.y], 1);
    atomicAdd(&g_cnt_out[s.z], 1); atomicAdd(&g_cnt_out[s.w], 1);
    atomicAdd(&g_cnt_in[d.x], 1);  atomicAdd(&g_cnt_in[d.y], 1);
    atomicAdd(&g_cnt_in[d.z], 1);  atomicAdd(&g_cnt_in[d.w], 1);
}

// W1 and W2 -> fp16, one pass
__global__ void prep_weights_kernel(const float* __restrict__ W1, const float* __restrict__ W2) {
    int i = blockIdx.x * blockDim.x + threadIdx.x;
    if (i < IN_DIM * HID) g_w1h[i] = __float2half(W1[i]);
    else if (i < IN_DIM * HID + HID * OUT_DIM) g_w2h[i - IN_DIM * HID] = __float2half(W2[i - IN_DIM * HID]);
}

// ---------------- CSR build (shfl scans) ----------------
__global__ __launch_bounds__(1024) void scan1_kernel() {
    __shared__ int wsum[32];
    int tid = threadIdx.x, lane = tid & 31, wid = tid >> 5;
    int i = blockIdx.x * 1024 + tid;
    int v = (i < N_NODES) ? g_cnt_in[i] : 0;
    int x = v;
#pragma unroll
    for (int o = 1; o < 32; o <<= 1) {
        int t = __shfl_up_sync(0xffffffff, x, o);
        if (lane >= o) x += t;
    }
    if (lane == 31) wsum[wid] = x;
    __syncthreads();
    if (wid == 0) {
        int w = wsum[lane];
#pragma unroll
        for (int o = 1; o < 32; o <<= 1) {
            int t = __shfl_up_sync(0xffffffff, w, o);
            if (lane >= o) w += t;
        }
        wsum[lane] = w;
    }
    __syncthreads();
    int base = (wid > 0) ? wsum[wid - 1] : 0;
    x += base;
    if (i < N_NODES) g_incl[i] = x;
    if (tid == 1023) g_bsum[blockIdx.x] = x;
}

__global__ __launch_bounds__(128) void scan2_kernel() {
    __shared__ int wsum[4];
    int tid = threadIdx.x, lane = tid & 31, wid = tid >> 5;
    int v = (tid < NB_SCAN) ? g_bsum[tid] : 0;
    int x = v;
#pragma unroll
    for (int o = 1; o < 32; o <<= 1) {
        int t = __shfl_up_sync(0xffffffff, x, o);
        if (lane >= o) x += t;
    }
    if (lane == 31) wsum[wid] = x;
    __syncthreads();
    int base = 0;
#pragma unroll
    for (int w = 0; w < 4; w++) base += (w < wid) ? wsum[w] : 0;
    if (tid < NB_SCAN) g_boff[tid] = x + base - v;   // exclusive
}

__global__ void scan3_kernel() {
    int i = blockIdx.x * blockDim.x + threadIdx.x;
    if (i >= N_NODES) return;
    int boff = g_boff[i >> 10];
    int excl = g_incl[i] - g_cnt_in[i] + boff;
    g_row_off[i] = excl;
    g_cursor[i]  = excl;
    if (i == N_NODES - 1) g_row_off[N_NODES] = g_incl[i] + boff;
}

__global__ void scatter_kernel(const int4* __restrict__ src4, const int4* __restrict__ dst4, int E4) {
    int i = blockIdx.x * blockDim.x + threadIdx.x;
    if (i >= E4) return;
    int4 s = src4[i], d = dst4[i];
    g_csr_src[atomicAdd(&g_cursor[d.x], 1)] = s.x;
    g_csr_src[atomicAdd(&g_cursor[d.y], 1)] = s.y;
    g_csr_src[atomicAdd(&g_cursor[d.z], 1)] = s.z;
    g_csr_src[atomicAdd(&g_cursor[d.w], 1)] = s.w;
}

// ---------------------------------------------------------------------------
// GEMM1 (HMMA, reg-lean A-prefetch): g_h1 = fp16((h @ W1) * deg_out^-1/2)
// ---------------------------------------------------------------------------
#define G1_SMEM (IN_DIM * 136 * 2)   // 69632 bytes
__global__ __launch_bounds__(256, 2) void gemm1_kernel(const float* __restrict__ A) {
    extern __shared__ __half Bsh[];   // [256][136]
    const int tid = threadIdx.x;
    const int wid = tid >> 5, lane = tid & 31;
    const int m0 = blockIdx.x * 128 + wid * 16;

    {
        const uint4* srcr = reinterpret_cast<const uint4*>(g_w1h + (size_t)tid * HID);
        uint4* dstr = reinterpret_cast<uint4*>(Bsh + (size_t)tid * 136);
#pragma unroll
        for (int i = 0; i < 16; i++) dstr[i] = srcr[i];
    }
    __syncthreads();

    const int g = lane >> 2, tg = lane & 3;
    const int row0 = m0 + g, row1 = m0 + g + 8;
    const bool ok0 = row0 < N_NODES, ok1 = row1 < N_NODES;
    const float* pa0 = A + (size_t)(ok0 ? row0 : 0) * IN_DIM + tg * 2;
    const float* pa1 = A + (size_t)(ok1 ? row1 : 0) * IN_DIM + tg * 2;

    const int k_off = (lane & 7) + ((lane >> 3) & 1) * 8;
    const int n_off = (lane >> 4) * 8;

    float acc[16][4];
#pragma unroll
    for (int t = 0; t < 16; t++)
#pragma unroll
        for (int j = 0; j < 4; j++) acc[t][j] = 0.f;

    const float2 z2 = make_float2(0.f, 0.f);
    float2 f;
    f = ok0 ? *reinterpret_cast<const float2*>(pa0) : z2;
    uint32_t na0 = h2u(__floats2half2_rn(f.x, f.y));
    f = ok1 ? *reinterpret_cast<const float2*>(pa1) : z2;
    uint32_t na1 = h2u(__floats2half2_rn(f.x, f.y));
    f = ok0 ? *reinterpret_cast<const float2*>(pa0 + 8) : z2;
    uint32_t na2 = h2u(__floats2half2_rn(f.x, f.y));
    f = ok1 ? *reinterpret_cast<const float2*>(pa1 + 8) : z2;
    uint32_t na3 = h2u(__floats2half2_rn(f.x, f.y));

    for (int kt = 0; kt < 16; kt++) {
        uint32_t a0 = na0, a1 = na1, a2 = na2, a3 = na3;
        if (kt < 15) {
            const int k1 = (kt + 1) * 16;
            f = ok0 ? *reinterpret_cast<const float2*>(pa0 + k1) : z2;
            na0 = h2u(__floats2half2_rn(f.x, f.y));
            f = ok1 ? *reinterpret_cast<const float2*>(pa1 + k1) : z2;
            na1 = h2u(__floats2half2_rn(f.x, f.y));
            f = ok0 ? *reinterpret_cast<const float2*>(pa0 + k1 + 8) : z2;
            na2 = h2u(__floats2half2_rn(f.x, f.y));
            f = ok1 ? *reinterpret_cast<const float2*>(pa1 + k1 + 8) : z2;
            na3 = h2u(__floats2half2_rn(f.x, f.y));
        }

        uint32_t base = smem_u32(Bsh + (size_t)(kt * 16 + k_off) * 136 + n_off);
#pragma unroll
        for (int p = 0; p < 8; p++) {
            uint32_t b0, b1, b2, b3;
            asm volatile("ldmatrix.sync.aligned.m8n8.x4.trans.shared.b16 {%0,%1,%2,%3}, [%4];"
                         : "=r"(b0), "=r"(b1), "=r"(b2), "=r"(b3)
                         : "r"(base + p * 32));
            mma16816(acc[2 * p],     a0, a1, a2, a3, b0, b1);
            mma16816(acc[2 * p + 1], a0, a1, a2, a3, b2, b3);
        }
    }

    float s0 = ok0 ? rsqrtf(fmaxf((float)g_cnt_out[row0], 1.f)) : 0.f;
    float s1 = ok1 ? rsqrtf(fmaxf((float)g_cnt_out[row1], 1.f)) : 0.f;
#pragma unroll
    for (int t = 0; t < 16; t++) {
        int col = t * 8 + tg * 2;
        if (ok0)
            *reinterpret_cast<__half2*>(g_h1 + (size_t)row0 * HID + col) =
                __floats2half2_rn(acc[t][0] * s0, acc[t][1] * s0);
        if (ok1)
            *reinterpret_cast<__half2*>(g_h1 + (size_t)row1 * HID + col) =
                __floats2half2_rn(acc[t][2] * s1, acc[t][3] * s1);
    }
}

// ---------------------------------------------------------------------------
// SpMM1 (pull, CSR, fp16 gather): warp per dst node, fused norm+bias+relu.
// ---------------------------------------------------------------------------
__global__ __launch_bounds__(256) void spmm1_csr_kernel(const float* __restrict__ b1) {
    int n = (blockIdx.x * blockDim.x + threadIdx.x) >> 5;
    if (n >= N_NODES) return;
    int lane = threadIdx.x & 31;
    int start = g_row_off[n];
    int end   = g_row_off[n + 1];

    float ax = 0.f, ay = 0.f, az = 0.f, aw = 0.f;
    for (int j = start; j < end; j += 32) {
        int s = 0;
        if (j + lane < end) s = __ldg(&g_csr_src[j + lane]);
        int cnt = min(32, end - j);
        if (cnt == 32) {
#pragma unroll 4
            for (int k = 0; k < 32; k++) {
                int sv = __shfl_sync(0xffffffff, s, k);
                uint2 pk = *reinterpret_cast<const uint2*>(g_h1 + (size_t)sv * HID + lane * 4);
                float2 f0 = __half22float2(*reinterpret_cast<__half2*>(&pk.x));
                float2 f1 = __half22float2(*reinterpret_cast<__half2*>(&pk.y));
                ax += f0.x; ay += f0.y; az += f1.x; aw += f1.y;
            }
        } else {
            for (int k = 0; k < cnt; k++) {
                int sv = __shfl_sync(0xffffffff, s, k);
                uint2 pk = *reinterpret_cast<const uint2*>(g_h1 + (size_t)sv * HID + lane * 4);
                float2 f0 = __half22float2(*reinterpret_cast<__half2*>(&pk.x));
                float2 f1 = __half22float2(*reinterpret_cast<__half2*>(&pk.y));
                ax += f0.x; ay += f0.y; az += f1.x; aw += f1.y;
            }
        }
    }

    float sc = rsqrtf(fmaxf((float)(end - start), 1.0f));
    float4 bb = *reinterpret_cast<const float4*>(b1 + lane * 4);
    float ox = fmaxf(ax * sc + bb.x, 0.f);
    float oy = fmaxf(ay * sc + bb.y, 0.f);
    float oz = fmaxf(az * sc + bb.z, 0.f);
    float ow = fmaxf(aw * sc + bb.w, 0.f);
    uint2 pk = make_uint2(h2u(__floats2half2_rn(ox, oy)), h2u(__floats2half2_rn(oz, ow)));
    *reinterpret_cast<uint2*>(g_x1h + (size_t)n * HID + lane * 4) = pk;
}

// ---------------------------------------------------------------------------
// GEMM2 (HMMA): g_x2 = fp16((x1 @ W2) * deg_out^-1/2)
// ---------------------------------------------------------------------------
#define G2_NPAD 56
__global__ __launch_bounds__(256) void gemm2_kernel() {
    __shared__ __half Wsh[HID * G2_NPAD];   // 14336 B
    const int tid = threadIdx.x;
    const int wid = tid >> 5, lane = tid & 31;
    const int m0 = blockIdx.x * 128 + wid * 16;

    for (int i = tid; i < HID * G2_NPAD; i += 256) {
        int r = i / G2_NPAD, c = i % G2_NPAD;
        Wsh[i] = (c < OUT_DIM) ? g_w2h[r * OUT_DIM + c] : __float2half(0.f);
    }
    __syncthreads();

    const int g = lane >> 2, tg = lane & 3;
    const int row0 = m0 + g, row1 = m0 + g + 8;
    const bool ok0 = row0 < N_NODES, ok1 = row1 < N_NODES;
    const __half* px0 = g_x1h + (size_t)(ok0 ? row0 : 0) * HID + tg * 2;
    const __half* px1 = g_x1h + (size_t)(ok1 ? row1 : 0) * HID + tg * 2;

    const int k_off = (lane & 7) + ((lane >> 3) & 1) * 8;
    const int n_off = (lane >> 4) * 8;

    float acc[6][4];
#pragma unroll
    for (int t = 0; t < 6; t++)
#pragma unroll
        for (int j = 0; j < 4; j++) acc[t][j] = 0.f;

    for (int kt = 0; kt < 8; kt++) {
        const int k0 = kt * 16;
        uint32_t a0 = ok0 ? *reinterpret_cast<const uint32_t*>(px0 + k0) : 0u;
        uint32_t a1 = ok1 ? *reinterpret_cast<const uint32_t*>(px1 + k0) : 0u;
        uint32_t a2 = ok0 ? *reinterpret_cast<const uint32_t*>(px0 + k0 + 8) : 0u;
        uint32_t a3 = ok1 ? *reinterpret_cast<const uint32_t*>(px1 + k0 + 8) : 0u;

        uint32_t base = smem_u32(Wsh + (size_t)(k0 + k_off) * G2_NPAD + n_off);
#pragma unroll
        for (int p = 0; p < 3; p++) {
            uint32_t b0, b1, b2, b3;
            asm volatile("ldmatrix.sync.aligned.m8n8.x4.trans.shared.b16 {%0,%1,%2,%3}, [%4];"
                         : "=r"(b0), "=r"(b1), "=r"(b2), "=r"(b3)
                         : "r"(base + p * 32));
            mma16816(acc[2 * p],     a0, a1, a2, a3, b0, b1);
            mma16816(acc[2 * p + 1], a0, a1, a2, a3, b2, b3);
        }
    }

    float s0 = ok0 ? rsqrtf(fmaxf((float)g_cnt_out[row0], 1.f)) : 0.f;
    float s1 = ok1 ? rsqrtf(fmaxf((float)g_cnt_out[row1], 1.f)) : 0.f;
#pragma unroll
    for (int t = 0; t < 5; t++) {
        int col = t * 8 + tg * 2;
        if (ok0)
            *reinterpret_cast<__half2*>(g_x2 + (size_t)row0 * OUT_DIM + col) =
                __floats2half2_rn(acc[t][0] * s0, acc[t][1] * s0);
        if (ok1)
            *reinterpret_cast<__half2*>(g_x2 + (size_t)row1 * OUT_DIM + col) =
                __floats2half2_rn(acc[t][2] * s1, acc[t][3] * s1);
    }
}

// ---------------------------------------------------------------------------
// SpMM2 (pull, CSR, fp16 gather) + fused norm + bias + log_softmax.
// ---------------------------------------------------------------------------
__global__ __launch_bounds__(256) void spmm2_csr_kernel(float* __restrict__ out,
                                                        const float* __restrict__ b2) {
    int n = (blockIdx.x * blockDim.x + threadIdx.x) >> 5;
    if (n >= N_NODES) return;
    int lane = threadIdx.x & 31;
    int half = lane >> 4;
    int hl   = lane & 15;
    bool act = hl < (OUT_DIM / 4);
    int start = g_row_off[n];
    int end   = g_row_off[n + 1];

    float ax = 0.f, ay = 0.f, az = 0.f, aw = 0.f;
    for (int j = start; j < end; j += 32) {
        int s = 0;
        if (j + lane < end) s = __ldg(&g_csr_src[j + lane]);
        int cnt = min(32, end - j);
        if (cnt == 32) {
#pragma unroll 4
            for (int k = 0; k < 32; k += 2) {
                int sv = __shfl_sync(0xffffffff, s, k + half);
                if (act) {
                    uint2 pk = *reinterpret_cast<const uint2*>(g_x2 + (size_t)sv * OUT_DIM + hl * 4);
                    float2 f0 = __half22float2(*reinterpret_cast<__half2*>(&pk.x));
                    float2 f1 = __half22float2(*reinterpret_cast<__half2*>(&pk.y));
                    ax += f0.x; ay += f0.y; az += f1.x; aw += f1.y;
                }
            }
        } else {
            for (int k = 0; k < cnt; k += 2) {
                int idx = k + half;
                bool ok = act && (idx < cnt);
                int sv = __shfl_sync(0xffffffff, s, idx < cnt ? idx : k);
                if (ok) {
                    uint2 pk = *reinterpret_cast<const uint2*>(g_x2 + (size_t)sv * OUT_DIM + hl * 4);
                    float2 f0 = __half22float2(*reinterpret_cast<__half2*>(&pk.x));
                    float2 f1 = __half22float2(*reinterpret_cast<__half2*>(&pk.y));
                    ax += f0.x; ay += f0.y; az += f1.x; aw += f1.y;
                }
            }
        }
    }
    ax += __shfl_down_sync(0xffffffff, ax, 16);
    ay += __shfl_down_sync(0xffffffff, ay, 16);
    az += __shfl_down_sync(0xffffffff, az, 16);
    aw += __shfl_down_sync(0xffffffff, aw, 16);

    bool fin = (lane < OUT_DIM / 4);
    float sc = rsqrtf(fmaxf((float)(end - start), 1.0f));
    float4 x = make_float4(-FLT_MAX, -FLT_MAX, -FLT_MAX, -FLT_MAX);
    if (fin) {
        float4 bb = *reinterpret_cast<const float4*>(b2 + lane * 4);
        x.x = ax * sc + bb.x;
        x.y = ay * sc + bb.y;
        x.z = az * sc + bb.z;
        x.w = aw * sc + bb.w;
    }

    float m = fmaxf(fmaxf(x.x, x.y), fmaxf(x.z, x.w));
#pragma unroll
    for (int o = 16; o > 0; o >>= 1) m = fmaxf(m, __shfl_xor_sync(0xffffffff, m, o));

    float se = 0.f;
    if (fin) se = expf(x.x - m) + expf(x.y - m) + expf(x.z - m) + expf(x.w - m);
#pragma unroll
    for (int o = 16; o > 0; o >>= 1) se += __shfl_xor_sync(0xffffffff, se, o);

    float lse = m + logf(se);
    if (fin) {
        float4 r = make_float4(x.x - lse, x.y - lse, x.z - lse, x.w - lse);
        *reinterpret_cast<float4*>(out + (size_t)n * OUT_DIM + lane * 4) = r;
    }
}

// ---------------------------------------------------------------------------
extern "C" void kernel_launch(void* const* d_in, const int* in_sizes, int n_in,
                              void* d_out, int out_size) {
    const float* h  = (const float*)d_in[0];
    const float* W1 = (const float*)d_in[1];
    const float* b1 = (const float*)d_in[2];
    const float* W2 = (const float*)d_in[3];
    const float* b2 = (const float*)d_in[4];
    const int* src  = (const int*)d_in[5];
    const int* dst  = (const int*)d_in[6];
    float* out      = (float*)d_out;
    const int E     = in_sizes[5];
    const int E4    = E / 4;

    // one-time host-side stream/event setup (no device memory involved)
    static cudaStream_t s2 = nullptr;
    static cudaEvent_t evFork = nullptr, evJoin = nullptr;
    if (!s2) {
        cudaStreamCreateWithFlags(&s2, cudaStreamNonBlocking);
        cudaEventCreateWithFlags(&evFork, cudaEventDisableTiming);
        cudaEventCreateWithFlags(&evJoin, cudaEventDisableTiming);
        cudaFuncSetAttribute(gemm1_kernel, cudaFuncAttributeMaxDynamicSharedMemorySize, G1_SMEM);
    }

    const int PREP_N = IN_DIM * HID + HID * OUT_DIM;
    // main stream: counts + weights + degree
    zero_counts_kernel<<<(N_NODES + 255) / 256, 256>>>();
    prep_weights_kernel<<<(PREP_N + 255) / 256, 256>>>(W1, W2);
    degree_kernel<<<(E4 + 255) / 256, 256>>>((const int4*)src, (const int4*)dst, E4);
    cudaEventRecord(evFork, 0);

    // branch A (stream s2): gemm1 — needs only h, W1(fp16), cnt_out
    cudaStreamWaitEvent(s2, evFork, 0);
    gemm1_kernel<<<(N_NODES + 127) / 128, 256, G1_SMEM, s2>>>(h);
    cudaEventRecord(evJoin, s2);

    // branch B (main stream): CSR build — independent of gemm1
    scan1_kernel<<<NB_SCAN, 1024>>>();
    scan2_kernel<<<1, 128>>>();
    scan3_kernel<<<(N_NODES + 255) / 256, 256>>>();
    scatter_kernel<<<(E4 + 255) / 256, 256>>>((const int4*)src, (const int4*)dst, E4);

    // join: spmm1 needs both CSR and g_h1
    cudaStreamWaitEvent(0, evJoin, 0);
    spmm1_csr_kernel<<<(N_NODES * 32 + 255) / 256, 256>>>(b1);
    gemm2_kernel<<<(N_NODES + 127) / 128, 256>>>();
    spmm2_csr_kernel<<<(N_NODES * 32 + 255) / 256, 256>>>(out, b2);
}

// round 15
// speedup vs baseline: 1.1191x; 1.0069x over previous
#include <cuda_runtime.h>
#include <cuda_fp16.h>
#include <math.h>
#include <float.h>
#include <stdint.h>

#define N_NODES 100000
#define IN_DIM  256
#define HID     128
#define OUT_DIM 40
#define E_MAX   3200000
#define NB_SCAN ((N_NODES + 1023) / 1024)   // 98

typedef unsigned long long u64;

// ---------------- scratch (device globals, allocation-free) ----------------
__device__ int   g_cnt_in[N_NODES];
__device__ int   g_cnt_out[N_NODES];
__device__ int   g_incl[N_NODES];
__device__ int   g_bsum[NB_SCAN];
__device__ int   g_boff[NB_SCAN];
__device__ int   g_row_off[N_NODES + 1];
__device__ int   g_cursor[N_NODES];
__device__ int   g_csr_src[E_MAX];
__device__ __half g_w1h[(size_t)IN_DIM * HID];     // W1 fp16 [k][n]
__device__ __half g_w2h[(size_t)HID * OUT_DIM];    // W2 fp16 [k][n]
__device__ __half g_h1[(size_t)N_NODES * HID];     // h1 fp16 (layer-1 pre-agg)
__device__ __half g_x1h[(size_t)N_NODES * HID];    // x1 fp16 (gemm2 input)
__device__ __half g_x2[(size_t)N_NODES * OUT_DIM]; // x2 fp16 (layer-2 pre-agg)

// ---------------- helpers ----------------
__device__ __forceinline__ uint32_t h2u(__half2 h) {
    uint32_t u;
    memcpy(&u, &h, 4);
    return u;
}
__device__ __forceinline__ uint32_t smem_u32(const void* p) {
    uint32_t a;
    asm("{ .reg .u64 t; cvta.to.shared.u64 t, %1; cvt.u32.u64 %0, t; }" : "=r"(a) : "l"(p));
    return a;
}
// mma.sync m16n8k16 f16 x f16 -> f32
__device__ __forceinline__ void mma16816(float* c, uint32_t a0, uint32_t a1, uint32_t a2,
                                         uint32_t a3, uint32_t b0, uint32_t b1) {
    asm volatile("mma.sync.aligned.m16n8k16.row.col.f32.f16.f16.f32 "
                 "{%0,%1,%2,%3}, {%4,%5,%6,%7}, {%8,%9}, {%0,%1,%2,%3};"
                 : "+f"(c[0]), "+f"(c[1]), "+f"(c[2]), "+f"(c[3])
                 : "r"(a0), "r"(a1), "r"(a2), "r"(a3), "r"(b0), "r"(b1));
}

// ---------------------------------------------------------------------------
__global__ void zero_counts_kernel() {
    int i = blockIdx.x * blockDim.x + threadIdx.x;
    if (i < N_NODES) { g_cnt_in[i] = 0; g_cnt_out[i] = 0; }
}

__global__ void degree_kernel(const int4* __restrict__ src4, const int4* __restrict__ dst4, int E4) {
    int i = blockIdx.x * blockDim.x + threadIdx.x;
    if (i >= E4) return;
    int4 s = src4[i], d = dst4[i];
    atomicAdd(&g_cnt_out[s.x], 1); atomicAdd(&g_cnt_out[s.y], 1);
    atomicAdd(&g_cnt_out[s.z], 1); atomicAdd(&g_cnt_out[s.w], 1);
    atomicAdd(&g_cnt_in[d.x], 1);  atomicAdd(&g_cnt_in[d.y], 1);
    atomicAdd(&g_cnt_in[d.z], 1);  atomicAdd(&g_cnt_in[d.w], 1);
}

// W1 and W2 -> fp16, one pass
__global__ void prep_weights_kernel(const float* __restrict__ W1, const float* __restrict__ W2) {
    int i = blockIdx.x * blockDim.x + threadIdx.x;
    if (i < IN_DIM * HID) g_w1h[i] = __float2half(W1[i]);
    else if (i < IN_DIM * HID + HID * OUT_DIM) g_w2h[i - IN_DIM * HID] = __float2half(W2[i - IN_DIM * HID]);
}

// ---------------- CSR build (shfl scans) ----------------
__global__ __launch_bounds__(1024) void scan1_kernel() {
    __shared__ int wsum[32];
    int tid = threadIdx.x, lane = tid & 31, wid = tid >> 5;
    int i = blockIdx.x * 1024 + tid;
    int v = (i < N_NODES) ? g_cnt_in[i] : 0;
    int x = v;
#pragma unroll
    for (int o = 1; o < 32; o <<= 1) {
        int t = __shfl_up_sync(0xffffffff, x, o);
        if (lane >= o) x += t;
    }
    if (lane == 31) wsum[wid] = x;
    __syncthreads();
    if (wid == 0) {
        int w = wsum[lane];
#pragma unroll
        for (int o = 1; o < 32; o <<= 1) {
            int t = __shfl_up_sync(0xffffffff, w, o);
            if (lane >= o) w += t;
        }
        wsum[lane] = w;
    }
    __syncthreads();
    int base = (wid > 0) ? wsum[wid - 1] : 0;
    x += base;
    if (i < N_NODES) g_incl[i] = x;
    if (tid == 1023) g_bsum[blockIdx.x] = x;
}

__global__ __launch_bounds__(128) void scan2_kernel() {
    __shared__ int wsum[4];
    int tid = threadIdx.x, lane = tid & 31, wid = tid >> 5;
    int v = (tid < NB_SCAN) ? g_bsum[tid] : 0;
    int x = v;
#pragma unroll
    for (int o = 1; o < 32; o <<= 1) {
        int t = __shfl_up_sync(0xffffffff, x, o);
        if (lane >= o) x += t;
    }
    if (lane == 31) wsum[wid] = x;
    __syncthreads();
    int base = 0;
#pragma unroll
    for (int w = 0; w < 4; w++) base += (w < wid) ? wsum[w] : 0;
    if (tid < NB_SCAN) g_boff[tid] = x + base - v;   // exclusive
}

__global__ void scan3_kernel() {
    int i = blockIdx.x * blockDim.x + threadIdx.x;
    if (i >= N_NODES) return;
    int boff = g_boff[i >> 10];
    int excl = g_incl[i] - g_cnt_in[i] + boff;
    g_row_off[i] = excl;
    g_cursor[i]  = excl;
    if (i == N_NODES - 1) g_row_off[N_NODES] = g_incl[i] + boff;
}

__global__ void scatter_kernel(const int4* __restrict__ src4, const int4* __restrict__ dst4, int E4) {
    int i = blockIdx.x * blockDim.x + threadIdx.x;
    if (i >= E4) return;
    int4 s = src4[i], d = dst4[i];
    g_csr_src[atomicAdd(&g_cursor[d.x], 1)] = s.x;
    g_csr_src[atomicAdd(&g_cursor[d.y], 1)] = s.y;
    g_csr_src[atomicAdd(&g_cursor[d.z], 1)] = s.z;
    g_csr_src[atomicAdd(&g_cursor[d.w], 1)] = s.w;
}

// ---------------------------------------------------------------------------
// GEMM1 (HMMA, reg-lean A-prefetch): g_h1 = fp16((h @ W1) * deg_out^-1/2)
// ---------------------------------------------------------------------------
#define G1_SMEM (IN_DIM * 136 * 2)   // 69632 bytes
__global__ __launch_bounds__(256, 2) void gemm1_kernel(const float* __restrict__ A) {
    extern __shared__ __half Bsh[];   // [256][136]
    const int tid = threadIdx.x;
    const int wid = tid >> 5, lane = tid & 31;
    const int m0 = blockIdx.x * 128 + wid * 16;

    {
        const uint4* srcr = reinterpret_cast<const uint4*>(g_w1h + (size_t)tid * HID);
        uint4* dstr = reinterpret_cast<uint4*>(Bsh + (size_t)tid * 136);
#pragma unroll
        for (int i = 0; i < 16; i++) dstr[i] = srcr[i];
    }
    __syncthreads();

    const int g = lane >> 2, tg = lane & 3;
    const int row0 = m0 + g, row1 = m0 + g + 8;
    const bool ok0 = row0 < N_NODES, ok1 = row1 < N_NODES;
    const float* pa0 = A + (size_t)(ok0 ? row0 : 0) * IN_DIM + tg * 2;
    const float* pa1 = A + (size_t)(ok1 ? row1 : 0) * IN_DIM + tg * 2;

    const int k_off = (lane & 7) + ((lane >> 3) & 1) * 8;
    const int n_off = (lane >> 4) * 8;

    float acc[16][4];
#pragma unroll
    for (int t = 0; t < 16; t++)
#pragma unroll
        for (int j = 0; j < 4; j++) acc[t][j] = 0.f;

    const float2 z2 = make_float2(0.f, 0.f);
    float2 f;
    f = ok0 ? *reinterpret_cast<const float2*>(pa0) : z2;
    uint32_t na0 = h2u(__floats2half2_rn(f.x, f.y));
    f = ok1 ? *reinterpret_cast<const float2*>(pa1) : z2;
    uint32_t na1 = h2u(__floats2half2_rn(f.x, f.y));
    f = ok0 ? *reinterpret_cast<const float2*>(pa0 + 8) : z2;
    uint32_t na2 = h2u(__floats2half2_rn(f.x, f.y));
    f = ok1 ? *reinterpret_cast<const float2*>(pa1 + 8) : z2;
    uint32_t na3 = h2u(__floats2half2_rn(f.x, f.y));

    for (int kt = 0; kt < 16; kt++) {
        uint32_t a0 = na0, a1 = na1, a2 = na2, a3 = na3;
        if (kt < 15) {
            const int k1 = (kt + 1) * 16;
            f = ok0 ? *reinterpret_cast<const float2*>(pa0 + k1) : z2;
            na0 = h2u(__floats2half2_rn(f.x, f.y));
            f = ok1 ? *reinterpret_cast<const float2*>(pa1 + k1) : z2;
            na1 = h2u(__floats2half2_rn(f.x, f.y));
            f = ok0 ? *reinterpret_cast<const float2*>(pa0 + k1 + 8) : z2;
            na2 = h2u(__floats2half2_rn(f.x, f.y));
            f = ok1 ? *reinterpret_cast<const float2*>(pa1 + k1 + 8) : z2;
            na3 = h2u(__floats2half2_rn(f.x, f.y));
        }

        uint32_t base = smem_u32(Bsh + (size_t)(kt * 16 + k_off) * 136 + n_off);
#pragma unroll
        for (int p = 0; p < 8; p++) {
            uint32_t b0, b1, b2, b3;
            asm volatile("ldmatrix.sync.aligned.m8n8.x4.trans.shared.b16 {%0,%1,%2,%3}, [%4];"
                         : "=r"(b0), "=r"(b1), "=r"(b2), "=r"(b3)
                         : "r"(base + p * 32));
            mma16816(acc[2 * p],     a0, a1, a2, a3, b0, b1);
            mma16816(acc[2 * p + 1], a0, a1, a2, a3, b2, b3);
        }
    }

    float s0 = ok0 ? rsqrtf(fmaxf((float)g_cnt_out[row0], 1.f)) : 0.f;
    float s1 = ok1 ? rsqrtf(fmaxf((float)g_cnt_out[row1], 1.f)) : 0.f;
#pragma unroll
    for (int t = 0; t < 16; t++) {
        int col = t * 8 + tg * 2;
        if (ok0)
            *reinterpret_cast<__half2*>(g_h1 + (size_t)row0 * HID + col) =
                __floats2half2_rn(acc[t][0] * s0, acc[t][1] * s0);
        if (ok1)
            *reinterpret_cast<__half2*>(g_h1 + (size_t)row1 * HID + col) =
                __floats2half2_rn(acc[t][2] * s1, acc[t][3] * s1);
    }
}

// ---------------------------------------------------------------------------
// SpMM1 (pull, CSR, fp16 gather): warp per dst node, DUAL-EDGE halves.
// Lanes 0-15 gather edge k, lanes 16-31 edge k+1 (same node); lane owns 8
// cols via uint4. Halves combined once at the end. Fused norm+bias+relu.
// ---------------------------------------------------------------------------
__global__ __launch_bounds__(256) void spmm1_csr_kernel(const float* __restrict__ b1) {
    int n = (blockIdx.x * blockDim.x + threadIdx.x) >> 5;
    if (n >= N_NODES) return;
    int lane = threadIdx.x & 31;
    int half = lane >> 4;
    int hl   = lane & 15;
    int start = g_row_off[n];
    int end   = g_row_off[n + 1];

    float acc[8];
#pragma unroll
    for (int i = 0; i < 8; i++) acc[i] = 0.f;

    for (int j = start; j < end; j += 32) {
        int s = 0;
        if (j + lane < end) s = __ldg(&g_csr_src[j + lane]);
        int cnt = min(32, end - j);
        if (cnt == 32) {
#pragma unroll 4
            for (int k = 0; k < 32; k += 2) {
                int sv = __shfl_sync(0xffffffff, s, k + half);
                uint4 pk = *reinterpret_cast<const uint4*>(g_h1 + (size_t)sv * HID + hl * 8);
                float2 f0 = __half22float2(*reinterpret_cast<__half2*>(&pk.x));
                float2 f1 = __half22float2(*reinterpret_cast<__half2*>(&pk.y));
                float2 f2 = __half22float2(*reinterpret_cast<__half2*>(&pk.z));
                float2 f3 = __half22float2(*reinterpret_cast<__half2*>(&pk.w));
                acc[0] += f0.x; acc[1] += f0.y; acc[2] += f1.x; acc[3] += f1.y;
                acc[4] += f2.x; acc[5] += f2.y; acc[6] += f3.x; acc[7] += f3.y;
            }
        } else {
            for (int k = 0; k < cnt; k += 2) {
                int idx = k + half;
                bool ok = idx < cnt;
                int sv = __shfl_sync(0xffffffff, s, ok ? idx : k);
                if (ok) {
                    uint4 pk = *reinterpret_cast<const uint4*>(g_h1 + (size_t)sv * HID + hl * 8);
                    float2 f0 = __half22float2(*reinterpret_cast<__half2*>(&pk.x));
                    float2 f1 = __half22float2(*reinterpret_cast<__half2*>(&pk.y));
                    float2 f2 = __half22float2(*reinterpret_cast<__half2*>(&pk.z));
                    float2 f3 = __half22float2(*reinterpret_cast<__half2*>(&pk.w));
                    acc[0] += f0.x; acc[1] += f0.y; acc[2] += f1.x; acc[3] += f1.y;
                    acc[4] += f2.x; acc[5] += f2.y; acc[6] += f3.x; acc[7] += f3.y;
                }
            }
        }
    }

    // combine halves into lanes 0-15
#pragma unroll
    for (int i = 0; i < 8; i++) acc[i] += __shfl_down_sync(0xffffffff, acc[i], 16);

    if (half == 0) {
        float sc = rsqrtf(fmaxf((float)(end - start), 1.0f));
        float4 b0 = *reinterpret_cast<const float4*>(b1 + hl * 8);
        float4 b4 = *reinterpret_cast<const float4*>(b1 + hl * 8 + 4);
        float o0 = fmaxf(acc[0] * sc + b0.x, 0.f), o1 = fmaxf(acc[1] * sc + b0.y, 0.f);
        float o2 = fmaxf(acc[2] * sc + b0.z, 0.f), o3 = fmaxf(acc[3] * sc + b0.w, 0.f);
        float o4 = fmaxf(acc[4] * sc + b4.x, 0.f), o5 = fmaxf(acc[5] * sc + b4.y, 0.f);
        float o6 = fmaxf(acc[6] * sc + b4.z, 0.f), o7 = fmaxf(acc[7] * sc + b4.w, 0.f);
        uint4 pk = make_uint4(h2u(__floats2half2_rn(o0, o1)), h2u(__floats2half2_rn(o2, o3)),
                              h2u(__floats2half2_rn(o4, o5)), h2u(__floats2half2_rn(o6, o7)));
        *reinterpret_cast<uint4*>(g_x1h + (size_t)n * HID + hl * 8) = pk;
    }
}

// ---------------------------------------------------------------------------
// GEMM2 (HMMA): g_x2 = fp16((x1 @ W2) * deg_out^-1/2)
// ---------------------------------------------------------------------------
#define G2_NPAD 56
__global__ __launch_bounds__(256) void gemm2_kernel() {
    __shared__ __half Wsh[HID * G2_NPAD];   // 14336 B
    const int tid = threadIdx.x;
    const int wid = tid >> 5, lane = tid & 31;
    const int m0 = blockIdx.x * 128 + wid * 16;

    for (int i = tid; i < HID * G2_NPAD; i += 256) {
        int r = i / G2_NPAD, c = i % G2_NPAD;
        Wsh[i] = (c < OUT_DIM) ? g_w2h[r * OUT_DIM + c] : __float2half(0.f);
    }
    __syncthreads();

    const int g = lane >> 2, tg = lane & 3;
    const int row0 = m0 + g, row1 = m0 + g + 8;
    const bool ok0 = row0 < N_NODES, ok1 = row1 < N_NODES;
    const __half* px0 = g_x1h + (size_t)(ok0 ? row0 : 0) * HID + tg * 2;
    const __half* px1 = g_x1h + (size_t)(ok1 ? row1 : 0) * HID + tg * 2;

    const int k_off = (lane & 7) + ((lane >> 3) & 1) * 8;
    const int n_off = (lane >> 4) * 8;

    float acc[6][4];
#pragma unroll
    for (int t = 0; t < 6; t++)
#pragma unroll
        for (int j = 0; j < 4; j++) acc[t][j] = 0.f;

    for (int kt = 0; kt < 8; kt++) {
        const int k0 = kt * 16;
        uint32_t a0 = ok0 ? *reinterpret_cast<const uint32_t*>(px0 + k0) : 0u;
        uint32_t a1 = ok1 ? *reinterpret_cast<const uint32_t*>(px1 + k0) : 0u;
        uint32_t a2 = ok0 ? *reinterpret_cast<const uint32_t*>(px0 + k0 + 8) : 0u;
        uint32_t a3 = ok1 ? *reinterpret_cast<const uint32_t*>(px1 + k0 + 8) : 0u;

        uint32_t base = smem_u32(Wsh + (size_t)(k0 + k_off) * G2_NPAD + n_off);
#pragma unroll
        for (int p = 0; p < 3; p++) {
            uint32_t b0, b1, b2, b3;
            asm volatile("ldmatrix.sync.aligned.m8n8.x4.trans.shared.b16 {%0,%1,%2,%3}, [%4];"
                         : "=r"(b0), "=r"(b1), "=r"(b2), "=r"(b3)
                         : "r"(base + p * 32));
            mma16816(acc[2 * p],     a0, a1, a2, a3, b0, b1);
            mma16816(acc[2 * p + 1], a0, a1, a2, a3, b2, b3);
        }
    }

    float s0 = ok0 ? rsqrtf(fmaxf((float)g_cnt_out[row0], 1.f)) : 0.f;
    float s1 = ok1 ? rsqrtf(fmaxf((float)g_cnt_out[row1], 1.f)) : 0.f;
#pragma unroll
    for (int t = 0; t < 5; t++) {
        int col = t * 8 + tg * 2;
        if (ok0)
            *reinterpret_cast<__half2*>(g_x2 + (size_t)row0 * OUT_DIM + col) =
                __floats2half2_rn(acc[t][0] * s0, acc[t][1] * s0);
        if (ok1)
            *reinterpret_cast<__half2*>(g_x2 + (size_t)row1 * OUT_DIM + col) =
                __floats2half2_rn(acc[t][2] * s1, acc[t][3] * s1);
    }
}

// ---------------------------------------------------------------------------
// SpMM2 (pull, CSR, fp16 gather) + fused norm + bias + log_softmax.
// ---------------------------------------------------------------------------
__global__ __launch_bounds__(256) void spmm2_csr_kernel(float* __restrict__ out,
                                                        const float* __restrict__ b2) {
    int n = (blockIdx.x * blockDim.x + threadIdx.x) >> 5;
    if (n >= N_NODES) return;
    int lane = threadIdx.x & 31;
    int half = lane >> 4;
    int hl   = lane & 15;
    bool act = hl < (OUT_DIM / 4);
    int start = g_row_off[n];
    int end   = g_row_off[n + 1];

    float ax = 0.f, ay = 0.f, az = 0.f, aw = 0.f;
    for (int j = start; j < end; j += 32) {
        int s = 0;
        if (j + lane < end) s = __ldg(&g_csr_src[j + lane]);
        int cnt = min(32, end - j);
        if (cnt == 32) {
#pragma unroll 4
            for (int k = 0; k < 32; k += 2) {
                int sv = __shfl_sync(0xffffffff, s, k + half);
                if (act) {
                    uint2 pk = *reinterpret_cast<const uint2*>(g_x2 + (size_t)sv * OUT_DIM + hl * 4);
                    float2 f0 = __half22float2(*reinterpret_cast<__half2*>(&pk.x));
                    float2 f1 = __half22float2(*reinterpret_cast<__half2*>(&pk.y));
                    ax += f0.x; ay += f0.y; az += f1.x; aw += f1.y;
                }
            }
        } else {
            for (int k = 0; k < cnt; k += 2) {
                int idx = k + half;
                bool ok = act && (idx < cnt);
                int sv = __shfl_sync(0xffffffff, s, idx < cnt ? idx : k);
                if (ok) {
                    uint2 pk = *reinterpret_cast<const uint2*>(g_x2 + (size_t)sv * OUT_DIM + hl * 4);
                    float2 f0 = __half22float2(*reinterpret_cast<__half2*>(&pk.x));
                    float2 f1 = __half22float2(*reinterpret_cast<__half2*>(&pk.y));
                    ax += f0.x; ay += f0.y; az += f1.x; aw += f1.y;
                }
            }
        }
    }
    ax += __shfl_down_sync(0xffffffff, ax, 16);
    ay += __shfl_down_sync(0xffffffff, ay, 16);
    az += __shfl_down_sync(0xffffffff, az, 16);
    aw += __shfl_down_sync(0xffffffff, aw, 16);

    bool fin = (lane < OUT_DIM / 4);
    float sc = rsqrtf(fmaxf((float)(end - start), 1.0f));
    float4 x = make_float4(-FLT_MAX, -FLT_MAX, -FLT_MAX, -FLT_MAX);
    if (fin) {
        float4 bb = *reinterpret_cast<const float4*>(b2 + lane * 4);
        x.x = ax * sc + bb.x;
        x.y = ay * sc + bb.y;
        x.z = az * sc + bb.z;
        x.w = aw * sc + bb.w;
    }

    float m = fmaxf(fmaxf(x.x, x.y), fmaxf(x.z, x.w));
#pragma unroll
    for (int o = 16; o > 0; o >>= 1) m = fmaxf(m, __shfl_xor_sync(0xffffffff, m, o));

    float se = 0.f;
    if (fin) se = expf(x.x - m) + expf(x.y - m) + expf(x.z - m) + expf(x.w - m);
#pragma unroll
    for (int o = 16; o > 0; o >>= 1) se += __shfl_xor_sync(0xffffffff, se, o);

    float lse = m + logf(se);
    if (fin) {
        float4 r = make_float4(x.x - lse, x.y - lse, x.z - lse, x.w - lse);
        *reinterpret_cast<float4*>(out + (size_t)n * OUT_DIM + lane * 4) = r;
    }
}

// ---------------------------------------------------------------------------
extern "C" void kernel_launch(void* const* d_in, const int* in_sizes, int n_in,
                              void* d_out, int out_size) {
    const float* h  = (const float*)d_in[0];
    const float* W1 = (const float*)d_in[1];
    const float* b1 = (const float*)d_in[2];
    const float* W2 = (const float*)d_in[3];
    const float* b2 = (const float*)d_in[4];
    const int* src  = (const int*)d_in[5];
    const int* dst  = (const int*)d_in[6];
    float* out      = (float*)d_out;
    const int E     = in_sizes[5];
    const int E4    = E / 4;

    // one-time host-side stream/event setup (no device memory involved)
    static cudaStream_t s2 = nullptr;
    static cudaEvent_t evFork = nullptr, evJoin = nullptr;
    if (!s2) {
        cudaStreamCreateWithFlags(&s2, cudaStreamNonBlocking);
        cudaEventCreateWithFlags(&evFork, cudaEventDisableTiming);
        cudaEventCreateWithFlags(&evJoin, cudaEventDisableTiming);
        cudaFuncSetAttribute(gemm1_kernel, cudaFuncAttributeMaxDynamicSharedMemorySize, G1_SMEM);
    }

    const int PREP_N = IN_DIM * HID + HID * OUT_DIM;
    // main stream: counts + degree; s2: weight prep (independent)
    zero_counts_kernel<<<(N_NODES + 255) / 256, 256>>>();                                 // 1
    prep_weights_kernel<<<(PREP_N + 255) / 256, 256, 0, s2>>>(W1, W2);                    // 2 (s2)
    degree_kernel<<<(E4 + 255) / 256, 256>>>((const int4*)src, (const int4*)dst, E4);     // 3
    cudaEventRecord(evFork, 0);

    // branch A (s2): gemm1 — needs prep (s2 order) + cnt_out (evFork)
    cudaStreamWaitEvent(s2, evFork, 0);
    gemm1_kernel<<<(N_NODES + 127) / 128, 256, G1_SMEM, s2>>>(h);                         // 4 (s2, profiled)
    cudaEventRecord(evJoin, s2);

    // branch B (main stream): CSR build
    scan1_kernel<<<NB_SCAN, 1024>>>();
    scan2_kernel<<<1, 128>>>();
    scan3_kernel<<<(N_NODES + 255) / 256, 256>>>();
    scatter_kernel<<<(E4 + 255) / 256, 256>>>((const int4*)src, (const int4*)dst, E4);

    // join: spmm1 needs both CSR and g_h1
    cudaStreamWaitEvent(0, evJoin, 0);
    spmm1_csr_kernel<<<(N_NODES * 32 + 255) / 256, 256>>>(b1);
    gemm2_kernel<<<(N_NODES + 127) / 128, 256>>>();
    spmm2_csr_kernel<<<(N_NODES * 32 + 255) / 256, 256>>>(out, b2);
}